// round 17
// baseline (speedup 1.0000x reference)
#include <cuda_runtime.h>
#include <cuda_fp16.h>
#include <cstdint>

// Shapes (fixed for KANLayer_17265768530645)
#define B_SZ    8192
#define D_IN    512
#define D_OUT   128
#define X_MIN_F (-3.0f)
#define DENOM   6.00000001f
#define SCALE_F (15.0f / DENOM)

// GEMM: y[b,n] = sum_{k'} C[b,k'] * W'[n,k'],  K' = 8704
#define KSTEPS   544          // K'/16
#define NCHUNK   68           // K'/128
#define NSPLIT   4            // K-splits
#define KPART    17           // chunks per K-split

// W' as mma B-fragments, CHUNK-MAJOR (4KB per kstep: ((ks*4+wc)*2+h)*32+lane).
__device__ __align__(128) uint4 g_wf[KSTEPS * 4 * 2 * 32];          // 2.2 MB
// K-split partial outputs: [4][B][128] fp32
__device__ __align__(16)  float g_part[NSPLIT * (size_t)B_SZ * D_OUT]; // 16.8 MB
// Per-b-tile completion counters (zero-init; finisher resets -> graph-replay safe)
__device__ int g_cnt[64];

// ---------------- PTX helpers ----------------------------------------------
__device__ __forceinline__ void ldm4(uint32_t* a, uint32_t addr) {
    asm volatile("ldmatrix.sync.aligned.m8n8.x4.shared.b16 {%0,%1,%2,%3}, [%4];"
                 : "=r"(a[0]), "=r"(a[1]), "=r"(a[2]), "=r"(a[3]) : "r"(addr));
}
__device__ __forceinline__ void mma16816(float* c, const uint32_t* a,
                                         uint32_t b0, uint32_t b1) {
    asm volatile(
        "mma.sync.aligned.m16n8k16.row.col.f32.f16.f16.f32 "
        "{%0,%1,%2,%3}, {%4,%5,%6,%7}, {%8,%9}, {%0,%1,%2,%3};"
        : "+f"(c[0]), "+f"(c[1]), "+f"(c[2]), "+f"(c[3])
        : "r"(a[0]), "r"(a[1]), "r"(a[2]), "r"(a[3]), "r"(b0), "r"(b1));
}
__device__ __forceinline__ uint32_t h2u(__half2 h) {
    return *reinterpret_cast<uint32_t*>(&h);
}
// 128-thread named barrier (ids 1,2) — per-wm-group sync.
#define BARW(id) asm volatile("bar.sync %0, 128;" :: "r"(id) : "memory")

// ---------------------------------------------------------------------------
// W' prep (validated R7-R16, unchanged).
// ---------------------------------------------------------------------------
__global__ void kan_wprep(const float* __restrict__ w,    // (128, 512, 16)
                          const float* __restrict__ s)    // (128, 512)
{
    const int wc   = blockIdx.y;
    const int lane = threadIdx.x & 31;
    const int ks   = blockIdx.x * 4 + (threadIdx.x >> 5);

    uint32_t r[8];
    #pragma unroll
    for (int nf = 0; nf < 4; nf++) {
        const int n = wc * 32 + nf * 8 + (lane >> 2);
        #pragma unroll
        for (int h = 0; h < 2; h++) {
            const int k = ks * 16 + (lane & 3) * 2 + h * 8;
            float v0, v1;
            if (ks < 512) {
                v0 = w[(size_t)n * 8192 + k];
                v1 = w[(size_t)n * 8192 + k + 1];
            } else {
                const int kk = k - 8192;
                v0 = s[(size_t)n * 512 + kk];
                v1 = s[(size_t)n * 512 + kk + 1];
            }
            r[nf * 2 + h] = h2u(__floats2half2_rn(v0, v1));
        }
    }
    g_wf[((size_t)(ks * 4 + wc) * 2 + 0) * 32 + lane] = make_uint4(r[0], r[1], r[2], r[3]);
    g_wf[((size_t)(ks * 4 + wc) * 2 + 1) * 32 + lane] = make_uint4(r[4], r[5], r[6], r[7]);
}

// ---------------------------------------------------------------------------
// C-chunk builders (128-row tile). Thread: bb = tid>>1 (row), il0 = (tid&1)*4.
// Bank-correct swizzle: byte(b, cb) = b*256 + (cb ^ ((b&7)<<4)).
// Rows 0-63 built & consumed by warps 0-3; rows 64-127 by warps 4-7.
// ---------------------------------------------------------------------------
__device__ __forceinline__ void build_spline4(char* rb, uint32_t swb,
                                              float4 xv, int il0)
{
    float xs[4] = {xv.x, xv.y, xv.z, xv.w};
    #pragma unroll
    for (int e = 0; e < 4; e++) {
        const int il = il0 + e;
        float p = fminf(fmaxf((xs[e] - X_MIN_F) * SCALE_F, 0.0f), 15.0f);
        int   k0 = min((int)p, 14);
        float f  = p - (float)k0;
        *reinterpret_cast<uint4*>(rb + ((uint32_t)(il * 32)      ^ swb)) = make_uint4(0,0,0,0);
        *reinterpret_cast<uint4*>(rb + ((uint32_t)(il * 32 + 16) ^ swb)) = make_uint4(0,0,0,0);
        const uint32_t cb = (uint32_t)(il * 32 + k0 * 2);
        *reinterpret_cast<__half*>(rb + (cb ^ swb))       = __float2half_rn(1.0f - f);
        *reinterpret_cast<__half*>(rb + ((cb + 2) ^ swb)) = __float2half_rn(f);
    }
}

__device__ __forceinline__ void build_skip4(char* rb, uint32_t swb,
                                            const float* __restrict__ xp, int il0)
{
    #pragma unroll
    for (int v = 0; v < 8; v++) {
        float4 f0 = *reinterpret_cast<const float4*>(xp + v * 8);
        float4 f1 = *reinterpret_cast<const float4*>(xp + v * 8 + 4);
        uint4 pk = make_uint4(h2u(__floats2half2_rn(f0.x, f0.y)),
                              h2u(__floats2half2_rn(f0.z, f0.w)),
                              h2u(__floats2half2_rn(f1.x, f1.y)),
                              h2u(__floats2half2_rn(f1.z, f1.w)));
        *reinterpret_cast<uint4*>(rb + ((uint32_t)(il0 * 32 + v * 16) ^ swb)) = pk;
    }
}

// ---------------------------------------------------------------------------
// Main GEMM: grid (64, 4) = 256 CTAs -> 2 CTAs/SM. CTA = 128 rows x 128 outs
// x K'/4. Warp grid 2(M) x 4(N), warp tile 64x32. C double-buffered (64KB);
// B direct-LDG depth-2 ring. Per-wm-group named barriers. Fused final reduce.
// ---------------------------------------------------------------------------
__global__ __launch_bounds__(256, 2)
void kan_mma(const float* __restrict__ x,
             const float* __restrict__ bias,
             float* __restrict__ y)
{
    extern __shared__ __align__(128) char dsm[];
    char* cs = dsm;                     // 2 x 32768 (C: 128 rows x 256B)
    __shared__ int s_last;

    const int tid  = threadIdx.x;
    const int lane = tid & 31;
    const int w    = tid >> 5;
    const int wm   = w >> 2;            // 0..1  (64 rows each)
    const int wc   = w & 3;             // 0..3  (32 outs each)
    const int bt   = blockIdx.x;        // b-tile 0..63 (128 rows each)
    const int ksp  = blockIdx.y;        // K-split 0..3
    const int ch0  = ksp * KPART;
    const int kse  = (ch0 + KPART) * 8; // kstep end
    const int barid = 1 + (tid >> 7);   // group barrier: tid 0-127 -> 1, else 2

    float acc[4][4][4];                 // [A-frag p][n-frag][4]
    #pragma unroll
    for (int p = 0; p < 4; p++)
        #pragma unroll
        for (int nf = 0; nf < 4; nf++)
            #pragma unroll
            for (int v = 0; v < 4; v++)
                acc[p][nf][v] = 0.0f;

    const uint32_t cs32 = (uint32_t)__cvta_generic_to_shared(cs);
    const uint32_t swz    = (uint32_t)((lane & 7) << 4);
    const uint32_t achunk = (uint32_t)((lane >> 4) << 4);
    const uint32_t arowoff = (uint32_t)((wm * 64 + (lane & 15)) * 256);

    const int bb  = tid >> 1;           // 0..127 (C row; tid<128 -> rows 0-63)
    const int il0 = (tid & 1) * 4;      // 4 i-slots per thread
    const uint32_t swb = (uint32_t)((bb & 7) << 4);
    const float* xrow = x + (size_t)(bt * 128 + bb) * 512;

    // B fragment stream (direct from L2-resident g_wf).
    const char* gwb = reinterpret_cast<const char*>(g_wf);
    const uint32_t bwoff = (uint32_t)(wc * 1024 + lane * 16);
    auto ldB = [&](int ks, uint4& q0, uint4& q1) {
        const uint4* bp = reinterpret_cast<const uint4*>(gwb + (size_t)ks * 4096 + bwoff);
        q0 = __ldg(bp);
        q1 = __ldg(bp + 32);
    };

    // Depth-2 B register ring: slot ks&1 holds kstep ks.
    uint4 bq[2][2];
    ldB(ch0 * 8,     bq[0][0], bq[0][1]);
    ldB(ch0 * 8 + 1, bq[1][0], bq[1][1]);

    // Build C chunk ch0 (all ch0 in {0,17,34,51} < 64: spline).
    {
        float4 xv = *reinterpret_cast<const float4*>(xrow + ch0 * 8 + il0);
        build_spline4(cs + bb * 256, swb, xv, il0);
    }
    BARW(barid);

    for (int cl = 0; cl < KPART; cl++) {
        const int ch  = ch0 + cl;
        const int cur = cl & 1, nxt = cur ^ 1;

        float4 xpre = make_float4(0.f, 0.f, 0.f, 0.f);
        const bool haveNext  = (cl + 1 < KPART);
        const bool nextSplin = (ch + 1 < 64);
        if (haveNext && nextSplin)
            xpre = *reinterpret_cast<const float4*>(xrow + (ch + 1) * 8 + il0);

        const uint32_t abase = cs32 + (uint32_t)cur * 32768 + arowoff;

        #pragma unroll
        for (int ksl = 0; ksl < 8; ksl++) {
            const int ks = ch * 8 + ksl;
            const int slot = ks & 1;
            const uint4 r0 = bq[slot][0];
            const uint4 r1 = bq[slot][1];
            if (ks + 2 < kse) ldB(ks + 2, bq[slot][0], bq[slot][1]);

            const uint32_t koff = (achunk + (uint32_t)(ksl * 32)) ^ swz;

            #pragma unroll
            for (int p = 0; p < 4; p++) {
                uint32_t a[4];
                ldm4(a, abase + (uint32_t)p * 4096 + koff);
                mma16816(acc[p][0], a, r0.x, r0.y);
                mma16816(acc[p][1], a, r0.z, r0.w);
                mma16816(acc[p][2], a, r1.x, r1.y);
                mma16816(acc[p][3], a, r1.z, r1.w);
            }
        }

        if (haveNext) {
            char* rb = cs + nxt * 32768 + bb * 256;
            if (nextSplin) {
                build_spline4(rb, swb, xpre, il0);
            } else {
                build_skip4(rb, swb, xrow + (ch + 1 - 64) * 128 + il0 * 16, il0);
            }
            BARW(barid);
        }
    }

    // Epilogue: fp32 partials.
    float* yb = g_part + (size_t)ksp * (B_SZ * D_OUT)
                       + (size_t)(bt * 128 + wm * 64) * 128;
    #pragma unroll
    for (int p = 0; p < 4; p++) {
        const int r0 = p * 16 + (lane >> 2);
        #pragma unroll
        for (int nf = 0; nf < 4; nf++) {
            const int n0 = wc * 32 + nf * 8 + (lane & 3) * 2;
            *reinterpret_cast<float2*>(yb + (size_t)r0 * 128 + n0) =
                make_float2(acc[p][nf][0], acc[p][nf][1]);
            *reinterpret_cast<float2*>(yb + (size_t)(r0 + 8) * 128 + n0) =
                make_float2(acc[p][nf][2], acc[p][nf][3]);
        }
    }

    // Fused reduce: 4th CTA for this b-tile sums the 4 partials + bias.
    __threadfence();
    if (tid == 0) {
        int old = atomicAdd(&g_cnt[bt], 1);
        s_last = (old == 3) ? 1 : 0;
        if (old == 3) g_cnt[bt] = 0;    // self-reset for next launch/replay
    }
    __syncthreads();
    if (s_last) {
        __threadfence();                 // acquire other CTAs' partials
        const float4* pp = reinterpret_cast<const float4*>(g_part);
        const float4* b4 = reinterpret_cast<const float4*>(bias);
        float4* y4 = reinterpret_cast<float4*>(y);
        const int base = bt * 4096;      // float4 units within a slice
        const int S4 = B_SZ * D_OUT / 4; // slice stride in float4
        #pragma unroll 4
        for (int j = tid; j < 4096; j += 256) {
            float4 a = pp[base + j];
            float4 b = pp[base + j + S4];
            float4 c = pp[base + j + 2 * S4];
            float4 d = pp[base + j + 3 * S4];
            float4 bi = b4[j & 31];
            y4[base + j] = make_float4((a.x + b.x) + (c.x + d.x) + bi.x,
                                       (a.y + b.y) + (c.y + d.y) + bi.y,
                                       (a.z + b.z) + (c.z + d.z) + bi.z,
                                       (a.w + b.w) + (c.w + d.w) + bi.w);
        }
    }
}

// ---------------------------------------------------------------------------
// kernel_launch: inputs per metadata order: x, weights, skip_w, bias
// ---------------------------------------------------------------------------
#define SMEM_DYN (64 * 1024)

extern "C" void kernel_launch(void* const* d_in, const int* in_sizes, int n_in,
                              void* d_out, int out_size)
{
    const float* x    = (const float*)d_in[0];
    const float* w    = (const float*)d_in[1];
    const float* skip = (const float*)d_in[2];
    const float* bias = (const float*)d_in[3];
    float* y = (float*)d_out;

    cudaFuncSetAttribute(kan_mma, cudaFuncAttributeMaxDynamicSharedMemorySize,
                         SMEM_DYN);
    kan_wprep<<<dim3(136, 4), 128>>>(w, skip);
    kan_mma<<<dim3(64, NSPLIT), 256, SMEM_DYN>>>(x, bias, y);
}